// round 10
// baseline (speedup 1.0000x reference)
#include <cuda_runtime.h>
#include <cuda_bf16.h>
#include <cstdint>

// GATConv_74904229642448 — attention collapses to multiply-by-one (row-
// normalized alpha contracted only over its normalization axis):
//   out[n, j] = dot(x[n,:], W[(j&7)*64 + (j>>3), :]) + bias[j]
// => 4096x512x256 fp32 GEMM, adj unused.
//
// Split-bf16 3-term GEMM on mma.sync (tcgen05 unreachable on compute_103).
// R7: 8 warps, KC=64 (4 chunks), explicit frag double-buffering across kk
// steps (ldmatrix of kk+1 issued before MMAs of kk), term-major MMA order.

#define N_NODES 4096
#define IN_C    256
#define OUT_TOT 512
#define BM 128
#define BN 128
#define KC 64
#define NCHUNK (IN_C / KC)        // 4
#define PITCH 144                 // 64 bf16 * 2B + 16B pad (conflict-free ldm)
#define REGION (128 * PITCH)      // 18432 B per tile
#define BUFB (4u * REGION)        // Ah, Al, Bh, Bl
#define SMEMB (2u * BUFB)         // 147456 B double-buffered

#define XT (N_NODES * IN_C)
#define WT (OUT_TOT * IN_C)

__device__ __align__(16) __nv_bfloat16 g_xh[XT];
__device__ __align__(16) __nv_bfloat16 g_xl[XT];
__device__ __align__(16) __nv_bfloat16 g_wh[WT];
__device__ __align__(16) __nv_bfloat16 g_wl[WT];

static __device__ __forceinline__ uint32_t smem_u32(const void* p) {
    uint32_t a;
    asm("{ .reg .u64 t; cvta.to.shared.u64 t, %1; cvt.u32.u64 %0, t; }"
        : "=r"(a) : "l"(p));
    return a;
}

static __device__ __forceinline__ uint32_t pack2(__nv_bfloat16 a, __nv_bfloat16 b) {
    return ((uint32_t)__bfloat16_as_ushort(b) << 16) | (uint32_t)__bfloat16_as_ushort(a);
}

// ---------------- pre-pass: fp32 -> (hi, lo) bf16, W permuted ----------------
__global__ __launch_bounds__(256, 8)
void cvt_pre(const float* __restrict__ x, const float* __restrict__ W)
{
    const int i = blockIdx.x * 256 + threadIdx.x;   // one float4 per thread
    const float4* src;
    __nv_bfloat16 *dh, *dl;
    int di;
    if (i < XT / 4) {
        src = (const float4*)x + i;
        dh = g_xh; dl = g_xl; di = i * 4;
    } else {
        const int j = i - XT / 4;                   // < WT/4
        const int row = j >> 6;                     // permuted (output) row
        const int srow = (row & 7) * 64 + (row >> 3);
        src = (const float4*)W + srow * 64 + (j & 63);
        dh = g_wh; dl = g_wl; di = j * 4;
    }
    const float4 v = *src;
    __nv_bfloat16 h0 = __float2bfloat16(v.x);
    __nv_bfloat16 h1 = __float2bfloat16(v.y);
    __nv_bfloat16 h2 = __float2bfloat16(v.z);
    __nv_bfloat16 h3 = __float2bfloat16(v.w);
    __nv_bfloat16 l0 = __float2bfloat16(v.x - __bfloat162float(h0));
    __nv_bfloat16 l1 = __float2bfloat16(v.y - __bfloat162float(h1));
    __nv_bfloat16 l2 = __float2bfloat16(v.z - __bfloat162float(h2));
    __nv_bfloat16 l3 = __float2bfloat16(v.w - __bfloat162float(h3));
    *(uint2*)(dh + di) = make_uint2(pack2(h0, h1), pack2(h2, h3));
    *(uint2*)(dl + di) = make_uint2(pack2(l0, l1), pack2(l2, l3));
}

// ---------------- GEMM ----------------
static __device__ __forceinline__ void cp16(uint32_t dst, const __nv_bfloat16* src) {
    asm volatile("cp.async.cg.shared.global [%0], [%1], 16;"
                 :: "r"(dst), "l"(src) : "memory");
}

static __device__ __forceinline__ void ldm4(uint32_t d[4], uint32_t addr) {
    asm volatile("ldmatrix.sync.aligned.m8n8.x4.shared.b16 {%0,%1,%2,%3}, [%4];"
                 : "=r"(d[0]), "=r"(d[1]), "=r"(d[2]), "=r"(d[3]) : "r"(addr));
}

static __device__ __forceinline__ void mma16816(float c[4], const uint32_t a[4],
                                                uint32_t b0, uint32_t b1) {
    asm volatile(
        "mma.sync.aligned.m16n8k16.row.col.f32.bf16.bf16.f32 "
        "{%0,%1,%2,%3}, {%4,%5,%6,%7}, {%8,%9}, {%0,%1,%2,%3};"
        : "+f"(c[0]), "+f"(c[1]), "+f"(c[2]), "+f"(c[3])
        : "r"(a[0]), "r"(a[1]), "r"(a[2]), "r"(a[3]), "r"(b0), "r"(b1));
}

extern __shared__ __align__(16) unsigned char dynsmem[];

__global__ __launch_bounds__(256, 1)
void gat_mma4(const float* __restrict__ bias, float* __restrict__ out)
{
    const uint32_t S = smem_u32(dynsmem);

    const int tid  = threadIdx.x;
    const int lane = tid & 31;
    const int warp = tid >> 5;          // 0..7
    const int wm = (warp >> 2) * 64;    // 2 warp-rows of 64
    const int wn = (warp & 3) * 32;     // 4 warp-cols of 32
    const int m0 = blockIdx.y * BM;
    const int n0 = blockIdx.x * BN;

    // cp.async mapping: each thread copies 64B (4x16B contiguous) per region:
    // row = tid>>1, half = tid&1 (k elements half*32 .. +31).
    const int crow = tid >> 1;
    const int chal = (tid & 1) * 32;
    const __nv_bfloat16* pxh = g_xh + (size_t)(m0 + crow) * IN_C + chal;
    const __nv_bfloat16* pxl = g_xl + (size_t)(m0 + crow) * IN_C + chal;
    const __nv_bfloat16* pwh = g_wh + (size_t)(n0 + crow) * IN_C + chal;
    const __nv_bfloat16* pwl = g_wl + (size_t)(n0 + crow) * IN_C + chal;
    const uint32_t dst0 = (uint32_t)(crow * PITCH + chal * 2);

    float acc[4][4][4];
    #pragma unroll
    for (int t = 0; t < 4; t++)
        #pragma unroll
        for (int u = 0; u < 4; u++)
            #pragma unroll
            for (int e = 0; e < 4; e++)
                acc[t][u][e] = 0.f;

    // Double-buffered fragment registers (parity index).
    uint32_t ah[2][4][4], al[2][4][4], bh[2][2][4], bl[2][2][4];

    auto issue = [&](int c) {
        const uint32_t D = S + (uint32_t)(c & 1) * BUFB + dst0;
        const int go = c * KC;
        #pragma unroll
        for (int s = 0; s < 4; s++) {
            cp16(D + s * 16u,               pxh + go + s * 8);
            cp16(D + REGION + s * 16u,      pxl + go + s * 8);
            cp16(D + 2u * REGION + s * 16u, pwh + go + s * 8);
            cp16(D + 3u * REGION + s * 16u, pwl + go + s * 8);
        }
        asm volatile("cp.async.commit_group;" ::: "memory");
    };

    issue(0);

    #pragma unroll 1
    for (int c = 0; c < NCHUNK; c++) {
        asm volatile("cp.async.wait_group 0;" ::: "memory");
        __syncthreads();
        if (c + 1 < NCHUNK) issue(c + 1);

        const uint32_t AH = S + (uint32_t)(c & 1) * BUFB;
        const uint32_t AL = AH + REGION;
        const uint32_t BH = AH + 2u * REGION;
        const uint32_t BL = AH + 3u * REGION;

        // Load fragments for a given kk into parity buffer pb.
        auto ldfrag = [&](int pb, int kk) {
            #pragma unroll
            for (int t = 0; t < 4; t++) {
                uint32_t off = (uint32_t)((wm + t * 16 + (lane & 15)) * PITCH
                                          + kk * 32 + ((lane >> 4) << 4));
                ldm4(ah[pb][t], AH + off);
                ldm4(al[pb][t], AL + off);
            }
            #pragma unroll
            for (int u2 = 0; u2 < 2; u2++) {
                uint32_t off = (uint32_t)((wn + u2 * 16 + ((lane >> 4) << 3) + (lane & 7)) * PITCH
                                          + kk * 32 + ((lane >> 3) & 1) * 16);
                ldm4(bh[pb][u2], BH + off);
                ldm4(bl[pb][u2], BL + off);
            }
        };

        ldfrag(0, 0);

        #pragma unroll
        for (int kk = 0; kk < 4; kk++) {
            const int pb = kk & 1;
            if (kk + 1 < 4) ldfrag((kk + 1) & 1, kk + 1);   // prefetch next frags

            // Term-major MMA order: 16 independent MMAs between acc reuses.
            #pragma unroll
            for (int t = 0; t < 4; t++)
                #pragma unroll
                for (int u = 0; u < 4; u++) {
                    const int u2 = u >> 1, e = (u & 1) * 2;
                    mma16816(acc[t][u], ah[pb][t], bh[pb][u2][e], bh[pb][u2][e + 1]);
                }
            #pragma unroll
            for (int t = 0; t < 4; t++)
                #pragma unroll
                for (int u = 0; u < 4; u++) {
                    const int u2 = u >> 1, e = (u & 1) * 2;
                    mma16816(acc[t][u], ah[pb][t], bl[pb][u2][e], bl[pb][u2][e + 1]);
                }
            #pragma unroll
            for (int t = 0; t < 4; t++)
                #pragma unroll
                for (int u = 0; u < 4; u++) {
                    const int u2 = u >> 1, e = (u & 1) * 2;
                    mma16816(acc[t][u], al[pb][t], bh[pb][u2][e], bh[pb][u2][e + 1]);
                }
        }
    }

    // Epilogue: bias + store. m16n8 acc mapping:
    //   c0:(row=lane>>2, col=(lane&3)*2) c1:col+1 c2:row+8 c3:row+8,col+1
    #pragma unroll
    for (int u = 0; u < 4; u++) {
        const int col = n0 + wn + u * 8 + (lane & 3) * 2;
        const float2 bv = *(const float2*)(bias + col);
        #pragma unroll
        for (int t = 0; t < 4; t++) {
            const int row = m0 + wm + t * 16 + (lane >> 2);
            float2 o0 = make_float2(acc[t][u][0] + bv.x, acc[t][u][1] + bv.y);
            float2 o1 = make_float2(acc[t][u][2] + bv.x, acc[t][u][3] + bv.y);
            *(float2*)(out + (size_t)row * OUT_TOT + col) = o0;
            *(float2*)(out + (size_t)(row + 8) * OUT_TOT + col) = o1;
        }
    }
}

extern "C" void kernel_launch(void* const* d_in, const int* in_sizes, int n_in,
                              void* d_out, int out_size) {
    // metadata order: adj, x, W, att_src, att_dst, bias
    const float* x    = (const float*)d_in[1];
    const float* W    = (const float*)d_in[2];
    const float* bias = (const float*)d_in[5];
    float* out        = (float*)d_out;

    cudaFuncSetAttribute(gat_mma4, cudaFuncAttributeMaxDynamicSharedMemorySize,
                         (int)SMEMB);

    const int pre_blocks = (XT / 4 + WT / 4) / 256;      // 1152
    cvt_pre<<<pre_blocks, 256>>>(x, W);

    dim3 grid(OUT_TOT / BN, N_NODES / BM);               // (4, 32) = 128 CTAs
    gat_mma4<<<grid, 256, SMEMB>>>(bias, out);
}

// round 11
// speedup vs baseline: 1.2566x; 1.2566x over previous
#include <cuda_runtime.h>
#include <cuda_fp16.h>
#include <cstdint>

// GATConv_74904229642448 — attention collapses to multiply-by-one (row-
// normalized alpha contracted only over its normalization axis):
//   out[n, j] = dot(x[n,:], W[(j&7)*64 + (j>>3), :]) + bias[j]
// => 4096x512x256 fp32 GEMM, adj unused.
//
// Legacy mma.sync (tcgen05 unreachable on compute_103) rate-limits at
// ~512 MACs/cyc/SM => fewer MACs is the only lever. R11: 2-term fp16
// scheme (was 3-term bf16):
//   W  = Wh + 2^-11 * Wl'   (fp16 pair, ~22 mantissa bits, Wl' scaled to
//                            stay in fp16 normal range)
//   xh = rn_fp16(x)          (2^-12 relative rounding error)
//   out = xh*Wh + 2^-11 * (xh*Wl') + bias   (two fp32 accumulators)
// Expected rel_err ~1.4e-4 (gate: 1e-3).

#define N_NODES 4096
#define IN_C    256
#define OUT_TOT 512
#define BM 128
#define BN 128
#define KC 32
#define NCHUNK (IN_C / KC)        // 8
#define PITCH 80                  // 32 fp16 * 2B + 16B pad
#define REGION (128 * PITCH)      // 10240 B per tile
#define BUFB (3u * REGION)        // Xh, Wh, Wl
#define SMEMB (2u * BUFB)         // 61440 B double-buffered
#define WLSCALE 2048.0f           // 2^11
#define WLINV   4.8828125e-4f     // 2^-11

#define XT (N_NODES * IN_C)
#define WT (OUT_TOT * IN_C)

__device__ __align__(16) __half g_xh[XT];
__device__ __align__(16) __half g_wh[WT];
__device__ __align__(16) __half g_wl[WT];

static __device__ __forceinline__ uint32_t smem_u32(const void* p) {
    uint32_t a;
    asm("{ .reg .u64 t; cvta.to.shared.u64 t, %1; cvt.u32.u64 %0, t; }"
        : "=r"(a) : "l"(p));
    return a;
}

static __device__ __forceinline__ uint32_t packh(__half a, __half b) {
    return ((uint32_t)__half_as_ushort(b) << 16) | (uint32_t)__half_as_ushort(a);
}

// ---------------- pre-pass: x -> fp16; W -> (hi, scaled-lo) fp16, permuted ----
__global__ __launch_bounds__(256, 8)
void cvt_pre(const float* __restrict__ x, const float* __restrict__ W)
{
    const int i = blockIdx.x * 256 + threadIdx.x;   // one float4 per thread
    if (i < XT / 4) {
        const float4 v = ((const float4*)x)[i];
        __half h0 = __float2half_rn(v.x);
        __half h1 = __float2half_rn(v.y);
        __half h2 = __float2half_rn(v.z);
        __half h3 = __float2half_rn(v.w);
        *(uint2*)(g_xh + i * 4) = make_uint2(packh(h0, h1), packh(h2, h3));
    } else {
        const int j = i - XT / 4;                   // < WT/4
        const int row = j >> 6;                     // permuted (output) row
        const int srow = (row & 7) * 64 + (row >> 3);
        const float4 v = ((const float4*)W)[srow * 64 + (j & 63)];
        __half h0 = __float2half_rn(v.x);
        __half h1 = __float2half_rn(v.y);
        __half h2 = __float2half_rn(v.z);
        __half h3 = __float2half_rn(v.w);
        __half l0 = __float2half_rn((v.x - __half2float(h0)) * WLSCALE);
        __half l1 = __float2half_rn((v.y - __half2float(h1)) * WLSCALE);
        __half l2 = __float2half_rn((v.z - __half2float(h2)) * WLSCALE);
        __half l3 = __float2half_rn((v.w - __half2float(h3)) * WLSCALE);
        *(uint2*)(g_wh + j * 4) = make_uint2(packh(h0, h1), packh(h2, h3));
        *(uint2*)(g_wl + j * 4) = make_uint2(packh(l0, l1), packh(l2, l3));
    }
}

// ---------------- GEMM ----------------
static __device__ __forceinline__ void cp16(uint32_t dst, const __half* src) {
    asm volatile("cp.async.cg.shared.global [%0], [%1], 16;"
                 :: "r"(dst), "l"(src) : "memory");
}

static __device__ __forceinline__ void ldm4(uint32_t d[4], uint32_t addr) {
    asm volatile("ldmatrix.sync.aligned.m8n8.x4.shared.b16 {%0,%1,%2,%3}, [%4];"
                 : "=r"(d[0]), "=r"(d[1]), "=r"(d[2]), "=r"(d[3]) : "r"(addr));
}

static __device__ __forceinline__ void mma16816(float c[4], const uint32_t a[4],
                                                uint32_t b0, uint32_t b1) {
    asm volatile(
        "mma.sync.aligned.m16n8k16.row.col.f32.f16.f16.f32 "
        "{%0,%1,%2,%3}, {%4,%5,%6,%7}, {%8,%9}, {%0,%1,%2,%3};"
        : "+f"(c[0]), "+f"(c[1]), "+f"(c[2]), "+f"(c[3])
        : "r"(a[0]), "r"(a[1]), "r"(a[2]), "r"(a[3]), "r"(b0), "r"(b1));
}

extern __shared__ __align__(16) unsigned char dynsmem[];

__global__ __launch_bounds__(512, 1)
void gat_mma5(const float* __restrict__ bias, float* __restrict__ out)
{
    const uint32_t S = smem_u32(dynsmem);

    const int tid  = threadIdx.x;
    const int lane = tid & 31;
    const int warp = tid >> 5;          // 0..15
    const int wm = (warp >> 2) * 32;    // 4 warp-rows of 32
    const int wn = (warp & 3) * 32;     // 4 warp-cols of 32
    const int m0 = blockIdx.y * BM;
    const int n0 = blockIdx.x * BN;

    // cp.async mapping: each thread owns one (row, 16B-seg) of every region.
    const int r   = tid >> 2;            // 0..127
    const int seg = tid & 3;
    const __half* pxh = g_xh + (size_t)(m0 + r) * IN_C + seg * 8;
    const __half* pwh = g_wh + (size_t)(n0 + r) * IN_C + seg * 8;
    const __half* pwl = g_wl + (size_t)(n0 + r) * IN_C + seg * 8;
    const uint32_t dst0 = (uint32_t)(r * PITCH + seg * 16);

    float acc1[2][4][4], acc2[2][4][4];
    #pragma unroll
    for (int t = 0; t < 2; t++)
        #pragma unroll
        for (int u = 0; u < 4; u++)
            #pragma unroll
            for (int e = 0; e < 4; e++) {
                acc1[t][u][e] = 0.f;
                acc2[t][u][e] = 0.f;
            }

    auto issue = [&](int c) {
        const uint32_t D = S + (uint32_t)(c & 1) * BUFB + dst0;
        const int go = c * KC;
        cp16(D,                pxh + go);
        cp16(D + REGION,       pwh + go);
        cp16(D + 2u * REGION,  pwl + go);
        asm volatile("cp.async.commit_group;" ::: "memory");
    };

    issue(0);

    #pragma unroll 1
    for (int c = 0; c < NCHUNK; c++) {
        asm volatile("cp.async.wait_group 0;" ::: "memory");
        __syncthreads();
        if (c + 1 < NCHUNK) issue(c + 1);

        const uint32_t XH = S + (uint32_t)(c & 1) * BUFB;
        const uint32_t WH = XH + REGION;
        const uint32_t WL = XH + 2u * REGION;

        #pragma unroll
        for (int kk = 0; kk < 2; kk++) {
            uint32_t ah[2][4], bh[2][4], bl[2][4];
            #pragma unroll
            for (int t = 0; t < 2; t++) {
                uint32_t off = (uint32_t)((wm + t * 16 + (lane & 15)) * PITCH
                                          + kk * 32 + ((lane >> 4) << 4));
                ldm4(ah[t], XH + off);
            }
            #pragma unroll
            for (int u2 = 0; u2 < 2; u2++) {
                uint32_t off = (uint32_t)((wn + u2 * 16 + ((lane >> 4) << 3) + (lane & 7)) * PITCH
                                          + kk * 32 + ((lane >> 3) & 1) * 16);
                ldm4(bh[u2], WH + off);
                ldm4(bl[u2], WL + off);
            }
            #pragma unroll
            for (int t = 0; t < 2; t++)
                #pragma unroll
                for (int u = 0; u < 4; u++) {
                    const int u2 = u >> 1, e = (u & 1) * 2;
                    mma16816(acc1[t][u], ah[t], bh[u2][e], bh[u2][e + 1]);
                    mma16816(acc2[t][u], ah[t], bl[u2][e], bl[u2][e + 1]);
                }
        }
    }

    // Epilogue: out = acc1 + 2^-11 * acc2 + bias. m16n8 acc mapping:
    //   c0:(row=lane>>2, col=(lane&3)*2) c1:col+1 c2:row+8 c3:row+8,col+1
    #pragma unroll
    for (int u = 0; u < 4; u++) {
        const int col = n0 + wn + u * 8 + (lane & 3) * 2;
        const float2 bv = *(const float2*)(bias + col);
        #pragma unroll
        for (int t = 0; t < 2; t++) {
            const int row = m0 + wm + t * 16 + (lane >> 2);
            float2 o0, o1;
            o0.x = fmaf(WLINV, acc2[t][u][0], acc1[t][u][0]) + bv.x;
            o0.y = fmaf(WLINV, acc2[t][u][1], acc1[t][u][1]) + bv.y;
            o1.x = fmaf(WLINV, acc2[t][u][2], acc1[t][u][2]) + bv.x;
            o1.y = fmaf(WLINV, acc2[t][u][3], acc1[t][u][3]) + bv.y;
            *(float2*)(out + (size_t)row * OUT_TOT + col) = o0;
            *(float2*)(out + (size_t)(row + 8) * OUT_TOT + col) = o1;
        }
    }
}

extern "C" void kernel_launch(void* const* d_in, const int* in_sizes, int n_in,
                              void* d_out, int out_size) {
    // metadata order: adj, x, W, att_src, att_dst, bias
    const float* x    = (const float*)d_in[1];
    const float* W    = (const float*)d_in[2];
    const float* bias = (const float*)d_in[5];
    float* out        = (float*)d_out;

    cudaFuncSetAttribute(gat_mma5, cudaFuncAttributeMaxDynamicSharedMemorySize,
                         (int)SMEMB);

    const int pre_blocks = (XT / 4 + WT / 4) / 256;      // 1152
    cvt_pre<<<pre_blocks, 256>>>(x, W);

    dim3 grid(OUT_TOT / BN, N_NODES / BM);               // (4, 32) = 128 CTAs
    gat_mma5<<<grid, 512, SMEMB>>>(bias, out);
}

// round 14
// speedup vs baseline: 1.5532x; 1.2361x over previous
#include <cuda_runtime.h>
#include <cuda_fp16.h>
#include <cstdint>

// GATConv_74904229642448 — attention collapses to multiply-by-one (row-
// normalized alpha contracted only over its normalization axis):
//   out[n, j] = dot(x[n,:], W[(j&7)*64 + (j>>3), :]) + bias[j]
// => 4096x512x256 fp32 GEMM, adj unused.
//
// Legacy mma.sync rate-limits at ~512 MACs/cyc/SM and runs at ~79% issue
// efficiency in this structure => time scales with MMA count. R12: single-
// term fp16 GEMM (x and W both rounded to fp16, fp32 accumulate).
// Error model: x-rounding alone measured 2.07e-4 (R11); adding W-rounding
// of equal size => ~2.9e-4 expected, 3.4x under the 1e-3 gate.

#define N_NODES 4096
#define IN_C    256
#define OUT_TOT 512
#define BM 128
#define BN 128
#define KC 32
#define NCHUNK (IN_C / KC)        // 8
#define PITCH 80                  // 32 fp16 * 2B + 16B pad
#define REGION (128 * PITCH)      // 10240 B per tile
#define BUFB (2u * REGION)        // Xh, Wh
#define SMEMB (2u * BUFB)         // 40960 B double-buffered

#define XT (N_NODES * IN_C)
#define WT (OUT_TOT * IN_C)

__device__ __align__(16) __half g_xh[XT];
__device__ __align__(16) __half g_wh[WT];

static __device__ __forceinline__ uint32_t smem_u32(const void* p) {
    uint32_t a;
    asm("{ .reg .u64 t; cvta.to.shared.u64 t, %1; cvt.u32.u64 %0, t; }"
        : "=r"(a) : "l"(p));
    return a;
}

static __device__ __forceinline__ uint32_t packh(__half a, __half b) {
    return ((uint32_t)__half_as_ushort(b) << 16) | (uint32_t)__half_as_ushort(a);
}

// ---------------- pre-pass: x, W(permuted) -> fp16 ----------------
__global__ __launch_bounds__(256, 8)
void cvt_pre(const float* __restrict__ x, const float* __restrict__ W)
{
    const int i = blockIdx.x * 256 + threadIdx.x;   // one float4 per thread
    if (i < XT / 4) {
        const float4 v = ((const float4*)x)[i];
        *(uint2*)(g_xh + i * 4) =
            make_uint2(packh(__float2half_rn(v.x), __float2half_rn(v.y)),
                       packh(__float2half_rn(v.z), __float2half_rn(v.w)));
    } else {
        const int j = i - XT / 4;                   // < WT/4
        const int row = j >> 6;                     // permuted (output) row
        const int srow = (row & 7) * 64 + (row >> 3);
        const float4 v = ((const float4*)W)[srow * 64 + (j & 63)];
        *(uint2*)(g_wh + j * 4) =
            make_uint2(packh(__float2half_rn(v.x), __float2half_rn(v.y)),
                       packh(__float2half_rn(v.z), __float2half_rn(v.w)));
    }
}

// ---------------- GEMM ----------------
static __device__ __forceinline__ void cp16(uint32_t dst, const __half* src) {
    asm volatile("cp.async.cg.shared.global [%0], [%1], 16;"
                 :: "r"(dst), "l"(src) : "memory");
}

static __device__ __forceinline__ void ldm4(uint32_t d[4], uint32_t addr) {
    asm volatile("ldmatrix.sync.aligned.m8n8.x4.shared.b16 {%0,%1,%2,%3}, [%4];"
                 : "=r"(d[0]), "=r"(d[1]), "=r"(d[2]), "=r"(d[3]) : "r"(addr));
}

static __device__ __forceinline__ void mma16816(float c[4], const uint32_t a[4],
                                                uint32_t b0, uint32_t b1) {
    asm volatile(
        "mma.sync.aligned.m16n8k16.row.col.f32.f16.f16.f32 "
        "{%0,%1,%2,%3}, {%4,%5,%6,%7}, {%8,%9}, {%0,%1,%2,%3};"
        : "+f"(c[0]), "+f"(c[1]), "+f"(c[2]), "+f"(c[3])
        : "r"(a[0]), "r"(a[1]), "r"(a[2]), "r"(a[3]), "r"(b0), "r"(b1));
}

extern __shared__ __align__(16) unsigned char dynsmem[];

__global__ __launch_bounds__(512, 1)
void gat_mma6(const float* __restrict__ bias, float* __restrict__ out)
{
    const uint32_t S = smem_u32(dynsmem);

    const int tid  = threadIdx.x;
    const int lane = tid & 31;
    const int warp = tid >> 5;          // 0..15
    const int wm = (warp >> 2) * 32;    // 4 warp-rows of 32
    const int wn = (warp & 3) * 32;     // 4 warp-cols of 32
    const int m0 = blockIdx.y * BM;
    const int n0 = blockIdx.x * BN;

    // cp.async mapping: each thread owns one (row, 16B-seg) of each region.
    const int r   = tid >> 2;            // 0..127
    const int seg = tid & 3;
    const __half* pxh = g_xh + (size_t)(m0 + r) * IN_C + seg * 8;
    const __half* pwh = g_wh + (size_t)(n0 + r) * IN_C + seg * 8;
    const uint32_t dst0 = (uint32_t)(r * PITCH + seg * 16);

    float acc[2][4][4];
    #pragma unroll
    for (int t = 0; t < 2; t++)
        #pragma unroll
        for (int u = 0; u < 4; u++)
            #pragma unroll
            for (int e = 0; e < 4; e++)
                acc[t][u][e] = 0.f;

    auto issue = [&](int c) {
        const uint32_t D = S + (uint32_t)(c & 1) * BUFB + dst0;
        const int go = c * KC;
        cp16(D,           pxh + go);
        cp16(D + REGION,  pwh + go);
        asm volatile("cp.async.commit_group;" ::: "memory");
    };

    issue(0);

    #pragma unroll 1
    for (int c = 0; c < NCHUNK; c++) {
        asm volatile("cp.async.wait_group 0;" ::: "memory");
        __syncthreads();
        if (c + 1 < NCHUNK) issue(c + 1);

        const uint32_t XH = S + (uint32_t)(c & 1) * BUFB;
        const uint32_t WH = XH + REGION;

        #pragma unroll
        for (int kk = 0; kk < 2; kk++) {
            uint32_t ah[2][4], bh[2][4];
            #pragma unroll
            for (int t = 0; t < 2; t++) {
                uint32_t off = (uint32_t)((wm + t * 16 + (lane & 15)) * PITCH
                                          + kk * 32 + ((lane >> 4) << 4));
                ldm4(ah[t], XH + off);
            }
            #pragma unroll
            for (int u2 = 0; u2 < 2; u2++) {
                uint32_t off = (uint32_t)((wn + u2 * 16 + ((lane >> 4) << 3) + (lane & 7)) * PITCH
                                          + kk * 32 + ((lane >> 3) & 1) * 16);
                ldm4(bh[u2], WH + off);
            }
            #pragma unroll
            for (int t = 0; t < 2; t++)
                #pragma unroll
                for (int u = 0; u < 4; u++) {
                    const int u2 = u >> 1, e = (u & 1) * 2;
                    mma16816(acc[t][u], ah[t], bh[u2][e], bh[u2][e + 1]);
                }
        }
    }

    // Epilogue: bias + store. m16n8 acc mapping:
    //   c0:(row=lane>>2, col=(lane&3)*2) c1:col+1 c2:row+8 c3:row+8,col+1
    #pragma unroll
    for (int u = 0; u < 4; u++) {
        const int col = n0 + wn + u * 8 + (lane & 3) * 2;
        const float2 bv = *(const float2*)(bias + col);
        #pragma unroll
        for (int t = 0; t < 2; t++) {
            const int row = m0 + wm + t * 16 + (lane >> 2);
            float2 o0 = make_float2(acc[t][u][0] + bv.x, acc[t][u][1] + bv.y);
            float2 o1 = make_float2(acc[t][u][2] + bv.x, acc[t][u][3] + bv.y);
            *(float2*)(out + (size_t)row * OUT_TOT + col) = o0;
            *(float2*)(out + (size_t)(row + 8) * OUT_TOT + col) = o1;
        }
    }
}

extern "C" void kernel_launch(void* const* d_in, const int* in_sizes, int n_in,
                              void* d_out, int out_size) {
    // metadata order: adj, x, W, att_src, att_dst, bias
    const float* x    = (const float*)d_in[1];
    const float* W    = (const float*)d_in[2];
    const float* bias = (const float*)d_in[5];
    float* out        = (float*)d_out;

    cudaFuncSetAttribute(gat_mma6, cudaFuncAttributeMaxDynamicSharedMemorySize,
                         (int)SMEMB);

    const int pre_blocks = (XT / 4 + WT / 4) / 256;      // 1152
    cvt_pre<<<pre_blocks, 256>>>(x, W);

    dim3 grid(OUT_TOT / BN, N_NODES / BM);               // (4, 32) = 128 CTAs
    gat_mma6<<<grid, 512, SMEMB>>>(bias, out);
}

// round 15
// speedup vs baseline: 1.6775x; 1.0800x over previous
#include <cuda_runtime.h>
#include <cuda_fp16.h>
#include <cstdint>

// GATConv_74904229642448 — attention collapses to multiply-by-one (row-
// normalized alpha contracted only over its normalization axis):
//   out[n, j] = dot(x[n,:], W[(j&7)*64 + (j>>3), :]) + bias[j]
// => 4096x512x256 fp32 GEMM, adj unused.
//
// Single-term fp16 mma.sync GEMM (rel_err 2.8e-4 measured, gate 1e-3).
// R15: single-shot smem residency — the full K=256 operand pair (128 KB)
// is loaded in one cp.async volley; ONE barrier; then 128 MMAs/warp run
// with no synchronization at all (the R14 chunk machinery cost more than
// the compute it fed).

#define N_NODES 4096
#define IN_C    256
#define OUT_TOT 512
#define BM 128
#define BN 128
#define PITCH 528                 // 256 fp16 * 2B + 16B pad (conflict-free ldm)
#define REGION (128u * PITCH)     // 67584 B per operand tile
#define SMEMB (2u * REGION)       // 135168 B

#define XT (N_NODES * IN_C)
#define WT (OUT_TOT * IN_C)

__device__ __align__(16) __half g_xh[XT];
__device__ __align__(16) __half g_wh[WT];

static __device__ __forceinline__ uint32_t smem_u32(const void* p) {
    uint32_t a;
    asm("{ .reg .u64 t; cvta.to.shared.u64 t, %1; cvt.u32.u64 %0, t; }"
        : "=r"(a) : "l"(p));
    return a;
}

static __device__ __forceinline__ uint32_t packh(__half a, __half b) {
    return ((uint32_t)__half_as_ushort(b) << 16) | (uint32_t)__half_as_ushort(a);
}

// ---------------- pre-pass: x, W(permuted) -> fp16 ----------------
__global__ __launch_bounds__(256, 8)
void cvt_pre(const float* __restrict__ x, const float* __restrict__ W)
{
    const int i = blockIdx.x * 256 + threadIdx.x;   // one float4 per thread
    if (i < XT / 4) {
        const float4 v = ((const float4*)x)[i];
        *(uint2*)(g_xh + i * 4) =
            make_uint2(packh(__float2half_rn(v.x), __float2half_rn(v.y)),
                       packh(__float2half_rn(v.z), __float2half_rn(v.w)));
    } else {
        const int j = i - XT / 4;                   // < WT/4
        const int row = j >> 6;                     // permuted (output) row
        const int srow = (row & 7) * 64 + (row >> 3);
        const float4 v = ((const float4*)W)[srow * 64 + (j & 63)];
        *(uint2*)(g_wh + j * 4) =
            make_uint2(packh(__float2half_rn(v.x), __float2half_rn(v.y)),
                       packh(__float2half_rn(v.z), __float2half_rn(v.w)));
    }
}

// ---------------- GEMM ----------------
static __device__ __forceinline__ void cp16(uint32_t dst, const __half* src) {
    asm volatile("cp.async.cg.shared.global [%0], [%1], 16;"
                 :: "r"(dst), "l"(src) : "memory");
}

static __device__ __forceinline__ void ldm4(uint32_t d[4], uint32_t addr) {
    asm volatile("ldmatrix.sync.aligned.m8n8.x4.shared.b16 {%0,%1,%2,%3}, [%4];"
                 : "=r"(d[0]), "=r"(d[1]), "=r"(d[2]), "=r"(d[3]) : "r"(addr));
}

static __device__ __forceinline__ void mma16816(float c[4], const uint32_t a[4],
                                                uint32_t b0, uint32_t b1) {
    asm volatile(
        "mma.sync.aligned.m16n8k16.row.col.f32.f16.f16.f32 "
        "{%0,%1,%2,%3}, {%4,%5,%6,%7}, {%8,%9}, {%0,%1,%2,%3};"
        : "+f"(c[0]), "+f"(c[1]), "+f"(c[2]), "+f"(c[3])
        : "r"(a[0]), "r"(a[1]), "r"(a[2]), "r"(a[3]), "r"(b0), "r"(b1));
}

extern __shared__ __align__(16) unsigned char dynsmem[];

__global__ __launch_bounds__(512, 1)
void gat_mma7(const float* __restrict__ bias, float* __restrict__ out)
{
    const uint32_t S = smem_u32(dynsmem);
    const uint32_t XH = S;
    const uint32_t WH = S + REGION;

    const int tid  = threadIdx.x;
    const int lane = tid & 31;
    const int warp = tid >> 5;          // 0..15
    const int wm = (warp >> 2) * 32;    // 4 warp-rows of 32
    const int wn = (warp & 3) * 32;     // 4 warp-cols of 32
    const int m0 = blockIdx.y * BM;
    const int n0 = blockIdx.x * BN;

    // Load volley: 4 threads per row; each thread covers 8 x 16B segments
    // (seg = (tid&3) + 4*s), both regions. 16 cp.async per thread total.
    {
        const int r  = tid >> 2;             // 0..127
        const int s0 = tid & 3;
        const __half* px = g_xh + (size_t)(m0 + r) * IN_C + s0 * 8;
        const __half* pw = g_wh + (size_t)(n0 + r) * IN_C + s0 * 8;
        const uint32_t dx = XH + (uint32_t)(r * PITCH + s0 * 16);
        const uint32_t dw = WH + (uint32_t)(r * PITCH + s0 * 16);
        #pragma unroll
        for (int s = 0; s < 8; s++) {
            cp16(dx + s * 64u, px + s * 32);
            cp16(dw + s * 64u, pw + s * 32);
        }
        asm volatile("cp.async.commit_group;" ::: "memory");
    }

    float acc[2][4][4];
    #pragma unroll
    for (int t = 0; t < 2; t++)
        #pragma unroll
        for (int u = 0; u < 4; u++)
            #pragma unroll
            for (int e = 0; e < 4; e++)
                acc[t][u][e] = 0.f;

    asm volatile("cp.async.wait_group 0;" ::: "memory");
    __syncthreads();                       // the ONLY barrier before epilogue

    // 16 k-steps, no synchronization: 4 ldm4 + 8 MMA each.
    #pragma unroll
    for (int kk = 0; kk < 16; kk++) {
        uint32_t ah[2][4], bh[2][4];
        #pragma unroll
        for (int t = 0; t < 2; t++) {
            uint32_t off = (uint32_t)((wm + t * 16 + (lane & 15)) * PITCH
                                      + kk * 32 + ((lane >> 4) << 4));
            ldm4(ah[t], XH + off);
        }
        #pragma unroll
        for (int u2 = 0; u2 < 2; u2++) {
            uint32_t off = (uint32_t)((wn + u2 * 16 + ((lane >> 4) << 3) + (lane & 7)) * PITCH
                                      + kk * 32 + ((lane >> 3) & 1) * 16);
            ldm4(bh[u2], WH + off);
        }
        #pragma unroll
        for (int t = 0; t < 2; t++)
            #pragma unroll
            for (int u = 0; u < 4; u++) {
                const int u2 = u >> 1, e = (u & 1) * 2;
                mma16816(acc[t][u], ah[t], bh[u2][e], bh[u2][e + 1]);
            }
    }

    // Epilogue: bias + store. m16n8 acc mapping:
    //   c0:(row=lane>>2, col=(lane&3)*2) c1:col+1 c2:row+8 c3:row+8,col+1
    #pragma unroll
    for (int u = 0; u < 4; u++) {
        const int col = n0 + wn + u * 8 + (lane & 3) * 2;
        const float2 bv = *(const float2*)(bias + col);
        #pragma unroll
        for (int t = 0; t < 2; t++) {
            const int row = m0 + wm + t * 16 + (lane >> 2);
            float2 o0 = make_float2(acc[t][u][0] + bv.x, acc[t][u][1] + bv.y);
            float2 o1 = make_float2(acc[t][u][2] + bv.x, acc[t][u][3] + bv.y);
            *(float2*)(out + (size_t)row * OUT_TOT + col) = o0;
            *(float2*)(out + (size_t)(row + 8) * OUT_TOT + col) = o1;
        }
    }
}

extern "C" void kernel_launch(void* const* d_in, const int* in_sizes, int n_in,
                              void* d_out, int out_size) {
    // metadata order: adj, x, W, att_src, att_dst, bias
    const float* x    = (const float*)d_in[1];
    const float* W    = (const float*)d_in[2];
    const float* bias = (const float*)d_in[5];
    float* out        = (float*)d_out;

    cudaFuncSetAttribute(gat_mma7, cudaFuncAttributeMaxDynamicSharedMemorySize,
                         (int)SMEMB);

    const int pre_blocks = (XT / 4 + WT / 4) / 256;      // 1152
    cvt_pre<<<pre_blocks, 256>>>(x, W);

    dim3 grid(OUT_TOT / BN, N_NODES / BM);               // (4, 32) = 128 CTAs
    gat_mma7<<<grid, 512, SMEMB>>>(bias, out);
}